// round 1
// baseline (speedup 1.0000x reference)
#include <cuda_runtime.h>

#define NN 50000
#define NE 800000
#define L 128

// Scratch (allocation-free rule: __device__ globals)
__device__ float g_sent[NN * L];
__device__ float g_recv[NN * L];
__device__ float g_Weff[16 * L];   // W_en @ W1[0:128,:]
__device__ float g_b1eff[L];       // b1 + b_en@W1[0:128,:] + g@W1[384:392,:]

// ---------------------------------------------------------------------------
__global__ void zero_kernel() {
    const int total4 = NN * L / 4;
    float4 z = make_float4(0.f, 0.f, 0.f, 0.f);
    float4* s = reinterpret_cast<float4*>(g_sent);
    float4* r = reinterpret_cast<float4*>(g_recv);
    for (int i = blockIdx.x * blockDim.x + threadIdx.x; i < total4;
         i += gridDim.x * blockDim.x) {
        s[i] = z;
        r[i] = z;
    }
}

// Weff[i][j] = sum_k W_en[i][k] * W1[k][j]   (16 x 128)
__global__ void prep_weff(const float* __restrict__ W_en,
                          const float* __restrict__ W1) {
    int idx = blockIdx.x * blockDim.x + threadIdx.x;
    if (idx >= 16 * L) return;
    int i = idx >> 7;
    int j = idx & 127;
    float s = 0.f;
#pragma unroll 8
    for (int k = 0; k < L; k++) s += W_en[i * L + k] * W1[k * L + j];
    g_Weff[idx] = s;
}

// b1eff[j] = b1[j] + sum_k b_en[k]*W1[k][j] + sum_k g[k]*W1[384+k][j]
__global__ void prep_b1eff(const float* __restrict__ b_en,
                           const float* __restrict__ b1,
                           const float* __restrict__ W1,
                           const float* __restrict__ g) {
    int j = threadIdx.x;
    if (j >= L) return;
    float s = b1[j];
#pragma unroll 8
    for (int k = 0; k < L; k++) s += b_en[k] * W1[k * L + j];
#pragma unroll
    for (int k = 0; k < 8; k++) s += g[k] * W1[(3 * L + k) * L + j];
    g_b1eff[j] = s;
}

// ---------------------------------------------------------------------------
// Edge pass: per warp, per edge: h_e (128-vec) in registers, scatter-add into
// sent/recv via red.global.add.v4.f32, edge decoder dot via warp reduce.
__global__ __launch_bounds__(256) void edge_kernel(
    const float* __restrict__ edges, const int* __restrict__ senders,
    const int* __restrict__ receivers, const float* __restrict__ W_ee,
    const float* __restrict__ b_ee, const float* __restrict__ W_de,
    const float* __restrict__ b_de, float* __restrict__ edges_out) {
    int lane = threadIdx.x & 31;
    int warp = (blockIdx.x * blockDim.x + threadIdx.x) >> 5;
    int nwarp = (gridDim.x * blockDim.x) >> 5;
    int c = lane * 4;

    float4 w0 = *reinterpret_cast<const float4*>(W_ee + c);
    float4 w1 = *reinterpret_cast<const float4*>(W_ee + L + c);
    float4 w2 = *reinterpret_cast<const float4*>(W_ee + 2 * L + c);
    float4 bb = *reinterpret_cast<const float4*>(b_ee + c);
    float4 wd = *reinterpret_cast<const float4*>(W_de + c);
    float bd = b_de[0];

    for (int e = warp; e < NE; e += nwarp) {
        float x0 = __ldg(edges + 3 * e + 0);
        float x1 = __ldg(edges + 3 * e + 1);
        float x2 = __ldg(edges + 3 * e + 2);
        int s = senders[e];
        int r = receivers[e];

        float4 h;
        h.x = fmaf(x0, w0.x, fmaf(x1, w1.x, fmaf(x2, w2.x, bb.x)));
        h.y = fmaf(x0, w0.y, fmaf(x1, w1.y, fmaf(x2, w2.y, bb.y)));
        h.z = fmaf(x0, w0.z, fmaf(x1, w1.z, fmaf(x2, w2.z, bb.z)));
        h.w = fmaf(x0, w0.w, fmaf(x1, w1.w, fmaf(x2, w2.w, bb.w)));

        float* ps = g_sent + (size_t)s * L + c;
        float* pr = g_recv + (size_t)r * L + c;
        asm volatile("red.global.add.v4.f32 [%0], {%1, %2, %3, %4};" ::"l"(ps),
                     "f"(h.x), "f"(h.y), "f"(h.z), "f"(h.w)
                     : "memory");
        asm volatile("red.global.add.v4.f32 [%0], {%1, %2, %3, %4};" ::"l"(pr),
                     "f"(h.x), "f"(h.y), "f"(h.z), "f"(h.w)
                     : "memory");

        float p = h.x * wd.x + h.y * wd.y + h.z * wd.z + h.w * wd.w;
#pragma unroll
        for (int o = 16; o; o >>= 1) p += __shfl_xor_sync(0xffffffffu, p, o);
        if (lane == 0) edges_out[e] = p + bd;
    }
}

// ---------------------------------------------------------------------------
// Node pass: fused  x=[nodes|sent|recv] (K=272, encoder folded) -> relu GEMM
// -> layer2 GEMM -> decoder dot. Tile: 64 nodes x 128 cols, 256 threads.
__global__ __launch_bounds__(256) void mlp_kernel(
    const float* __restrict__ nodes, const float* __restrict__ W1,
    const float* __restrict__ W2, const float* __restrict__ b2,
    const float* __restrict__ W_dn, const float* __restrict__ b_dn,
    float* __restrict__ nodes_out) {
    __shared__ float Xs[64][8];
    __shared__ float Ws[8][L];
    __shared__ float H1[64][L];

    int tid = threadIdx.x;
    int lane = tid & 31;
    int warp = tid >> 5;
    int wr = warp * 8;        // 8 node rows per warp
    int c4 = lane * 4;        // 4 output cols per lane
    int tile0 = blockIdx.x * 64;

    int lrow = tid >> 2;            // 0..63 (X load row)
    int lpair = (tid & 3) * 2;      // 0,2,4,6 (X load col pair)

    float4 acc[8];
    {
        float4 be = *reinterpret_cast<const float4*>(g_b1eff + c4);
#pragma unroll
        for (int m = 0; m < 8; m++) acc[m] = be;
    }

    // ---- layer 1: K = 272 = 34 chunks of 8 ----
    for (int chunk = 0; chunk < 34; chunk++) {
        int k0 = chunk * 8;
        const float* src;
        int stride, koff;
        if (k0 < 16) {
            src = nodes; stride = 16; koff = k0;
        } else if (k0 < 16 + L) {
            src = g_sent; stride = L; koff = k0 - 16;
        } else {
            src = g_recv; stride = L; koff = k0 - 16 - L;
        }
        int node = tile0 + lrow;
        float2 v = make_float2(0.f, 0.f);
        if (node < NN)
            v = *reinterpret_cast<const float2*>(src + (size_t)node * stride +
                                                 koff + lpair);
        Xs[lrow][lpair] = v.x;
        Xs[lrow][lpair + 1] = v.y;

        int kr = k0 + warp;  // 8 rows loaded by the 8 warps
        const float* wsrc = (kr < 16) ? (g_Weff + kr * L + c4)
                                      : (W1 + (size_t)(kr + 112) * L + c4);
        *reinterpret_cast<float4*>(&Ws[warp][c4]) =
            *reinterpret_cast<const float4*>(wsrc);
        __syncthreads();

#pragma unroll
        for (int kk = 0; kk < 8; kk++) {
            float4 wv = *reinterpret_cast<const float4*>(&Ws[kk][c4]);
#pragma unroll
            for (int m = 0; m < 8; m++) {
                float a = Xs[wr + m][kk];
                acc[m].x = fmaf(a, wv.x, acc[m].x);
                acc[m].y = fmaf(a, wv.y, acc[m].y);
                acc[m].z = fmaf(a, wv.z, acc[m].z);
                acc[m].w = fmaf(a, wv.w, acc[m].w);
            }
        }
        __syncthreads();
    }

    // relu -> H1
#pragma unroll
    for (int m = 0; m < 8; m++) {
        float4 h = acc[m];
        h.x = fmaxf(h.x, 0.f);
        h.y = fmaxf(h.y, 0.f);
        h.z = fmaxf(h.z, 0.f);
        h.w = fmaxf(h.w, 0.f);
        *reinterpret_cast<float4*>(&H1[wr + m][c4]) = h;
    }
    __syncthreads();

    // ---- layer 2: K = 128 = 16 chunks of 8 ----
    float4 acc2[8];
    {
        float4 bv = *reinterpret_cast<const float4*>(b2 + c4);
#pragma unroll
        for (int m = 0; m < 8; m++) acc2[m] = bv;
    }
    for (int chunk = 0; chunk < 16; chunk++) {
        int k0 = chunk * 8;
        int kr = k0 + warp;
        *reinterpret_cast<float4*>(&Ws[warp][c4]) =
            *reinterpret_cast<const float4*>(W2 + (size_t)kr * L + c4);
        __syncthreads();
#pragma unroll
        for (int kk = 0; kk < 8; kk++) {
            float4 wv = *reinterpret_cast<const float4*>(&Ws[kk][c4]);
#pragma unroll
            for (int m = 0; m < 8; m++) {
                float a = H1[wr + m][k0 + kk];
                acc2[m].x = fmaf(a, wv.x, acc2[m].x);
                acc2[m].y = fmaf(a, wv.y, acc2[m].y);
                acc2[m].z = fmaf(a, wv.z, acc2[m].z);
                acc2[m].w = fmaf(a, wv.w, acc2[m].w);
            }
        }
        __syncthreads();
    }

    // ---- node decoder: dot(h2, W_dn) + b_dn ----
    float4 wd = *reinterpret_cast<const float4*>(W_dn + c4);
    float bd = b_dn[0];
#pragma unroll
    for (int m = 0; m < 8; m++) {
        float p = acc2[m].x * wd.x + acc2[m].y * wd.y + acc2[m].z * wd.z +
                  acc2[m].w * wd.w;
#pragma unroll
        for (int o = 16; o; o >>= 1) p += __shfl_xor_sync(0xffffffffu, p, o);
        int node = tile0 + wr + m;
        if (lane == 0 && node < NN) nodes_out[node] = p + bd;
    }
}

// ---------------------------------------------------------------------------
extern "C" void kernel_launch(void* const* d_in, const int* in_sizes, int n_in,
                              void* d_out, int out_size) {
    const float* nodes     = (const float*)d_in[0];
    const float* edges     = (const float*)d_in[1];
    const float* globals_  = (const float*)d_in[2];
    const int*   senders   = (const int*)d_in[3];
    const int*   receivers = (const int*)d_in[4];
    const float* W_en = (const float*)d_in[5];
    const float* b_en = (const float*)d_in[6];
    const float* W_ee = (const float*)d_in[7];
    const float* b_ee = (const float*)d_in[8];
    const float* W1   = (const float*)d_in[9];
    const float* b1   = (const float*)d_in[10];
    const float* W2   = (const float*)d_in[11];
    const float* b2   = (const float*)d_in[12];
    const float* W_dn = (const float*)d_in[13];
    const float* b_dn = (const float*)d_in[14];
    const float* W_de = (const float*)d_in[15];
    const float* b_de = (const float*)d_in[16];

    float* out = (float*)d_out;
    float* nodes_out = out;          // [50000]
    float* edges_out = out + NN;     // [800000]

    zero_kernel<<<2048, 256>>>();
    prep_weff<<<8, 256>>>(W_en, W1);
    prep_b1eff<<<1, 128>>>(b_en, b1, W1, globals_);
    edge_kernel<<<4096, 256>>>(edges, senders, receivers, W_ee, b_ee, W_de,
                               b_de, edges_out);
    mlp_kernel<<<(NN + 63) / 64, 256>>>(nodes, W1, W2, b2, W_dn, b_dn,
                                        nodes_out);
}

// round 2
// speedup vs baseline: 7.2233x; 7.2233x over previous
#include <cuda_runtime.h>

#define NN 50000
#define NE 800000
#define L 128
#define KEFF 24   // 16 node feats + 3 agg_s + 1 cnt_s + 3 agg_r + 1 cnt_r

// Scratch (__device__ globals; no allocation allowed)
__device__ float g_aggs[NN * 4];        // {sum x0, x1, x2, count} by sender
__device__ float g_aggr[NN * 4];        // same by receiver
__device__ float g_W1eff[L * KEFF];     // [j][k] j-major, folded layer-1 weight
__device__ float g_b1eff[L];            // folded layer-1 bias
__device__ float g_w2d[L];              // W2 @ W_dn  (layer2+decoder folded)
__device__ float g_cd[1];               // b2.W_dn + b_dn
__device__ float g_edec[4];             // {W_ee@W_de (3), b_ee.W_de + b_de}

// ---------------------------------------------------------------------------
// prep: fold all linear ops + zero the aggregation buffers.
// grid: 64 blocks x 256. Threads 0..3071 compute W1eff entries, next ranges
// compute the small vectors/scalars; ALL threads grid-stride zero agg arrays.
__global__ __launch_bounds__(256) void prep_kernel(
    const float* __restrict__ g, const float* __restrict__ W_en,
    const float* __restrict__ b_en, const float* __restrict__ W_ee,
    const float* __restrict__ b_ee, const float* __restrict__ W1,
    const float* __restrict__ b1, const float* __restrict__ W2,
    const float* __restrict__ b2, const float* __restrict__ W_dn,
    const float* __restrict__ b_dn, const float* __restrict__ W_de,
    const float* __restrict__ b_de) {
    int t = blockIdx.x * blockDim.x + threadIdx.x;

    if (t < L * KEFF) {
        int j = t & (L - 1);
        int k = t >> 7;  // 0..23
        float s = 0.f;
        if (k < 16) {
            // W_en(16xL) @ W1[0:L]  -> W1eff[j][k]
#pragma unroll 8
            for (int m = 0; m < L; m++) s += W_en[k * L + m] * W1[m * L + j];
        } else if (k < 19) {
            int i = k - 16;  // W_ee(3xL) @ W1[L:2L]
#pragma unroll 8
            for (int m = 0; m < L; m++) s += W_ee[i * L + m] * W1[(L + m) * L + j];
        } else if (k == 19) {
#pragma unroll 8
            for (int m = 0; m < L; m++) s += b_ee[m] * W1[(L + m) * L + j];
        } else if (k < 23) {
            int i = k - 20;  // W_ee(3xL) @ W1[2L:3L]
#pragma unroll 8
            for (int m = 0; m < L; m++) s += W_ee[i * L + m] * W1[(2 * L + m) * L + j];
        } else {
#pragma unroll 8
            for (int m = 0; m < L; m++) s += b_ee[m] * W1[(2 * L + m) * L + j];
        }
        g_W1eff[j * KEFF + k] = s;
    } else if (t < L * KEFF + L) {
        int j = t - L * KEFF;  // b1eff
        float s = b1[j];
#pragma unroll 8
        for (int m = 0; m < L; m++) s += b_en[m] * W1[m * L + j];
#pragma unroll
        for (int m = 0; m < 8; m++) s += g[m] * W1[(3 * L + m) * L + j];
        g_b1eff[j] = s;
    } else if (t < L * KEFF + 2 * L) {
        int k = t - L * KEFF - L;  // w2d[k] = sum_j W2[k][j] * W_dn[j]
        float s = 0.f;
#pragma unroll 8
        for (int j = 0; j < L; j++) s += W2[k * L + j] * W_dn[j];
        g_w2d[k] = s;
    } else if (t == L * KEFF + 2 * L) {
        float s = b_dn[0];
        for (int j = 0; j < L; j++) s += b2[j] * W_dn[j];
        g_cd[0] = s;
    } else if (t <= L * KEFF + 2 * L + 3) {
        int i = t - (L * KEFF + 2 * L + 1);  // edge decoder fold
        float s = 0.f;
#pragma unroll 8
        for (int m = 0; m < L; m++) s += W_ee[i * L + m] * W_de[m];
        g_edec[i] = s;
    } else if (t == L * KEFF + 2 * L + 4) {
        float s = b_de[0];
        for (int m = 0; m < L; m++) s += b_ee[m] * W_de[m];
        g_edec[3] = s;
    }

    // zero agg buffers (all threads, grid-stride, float4)
    const int total4 = NN * 4 / 4;  // NN float4s per array
    float4 z = make_float4(0.f, 0.f, 0.f, 0.f);
    float4* as = reinterpret_cast<float4*>(g_aggs);
    float4* ar = reinterpret_cast<float4*>(g_aggr);
    for (int i = t; i < total4; i += gridDim.x * blockDim.x) {
        as[i] = z;
        ar[i] = z;
    }
}

// ---------------------------------------------------------------------------
// Edge pass: one thread per edge. 16B atomic per endpoint + 3-dot decoder.
__global__ __launch_bounds__(256) void edge_kernel(
    const float* __restrict__ edges, const int* __restrict__ senders,
    const int* __restrict__ receivers, float* __restrict__ edges_out) {
    int e = blockIdx.x * blockDim.x + threadIdx.x;
    if (e >= NE) return;

    float w0 = g_edec[0], w1 = g_edec[1], w2 = g_edec[2], c = g_edec[3];

    float x0 = __ldg(edges + 3 * e + 0);
    float x1 = __ldg(edges + 3 * e + 1);
    float x2 = __ldg(edges + 3 * e + 2);
    int s = senders[e];
    int r = receivers[e];

    float* ps = g_aggs + 4 * s;
    float* pr = g_aggr + 4 * r;
    asm volatile("red.global.add.v4.f32 [%0], {%1, %2, %3, %4};" ::"l"(ps),
                 "f"(x0), "f"(x1), "f"(x2), "f"(1.0f)
                 : "memory");
    asm volatile("red.global.add.v4.f32 [%0], {%1, %2, %3, %4};" ::"l"(pr),
                 "f"(x0), "f"(x1), "f"(x2), "f"(1.0f)
                 : "memory");

    edges_out[e] = fmaf(x0, w0, fmaf(x1, w1, fmaf(x2, w2, c)));
}

// ---------------------------------------------------------------------------
// Node pass: one thread per node. K=24 folded layer-1, relu, 128-dot decoder.
__global__ __launch_bounds__(256) void node_kernel(
    const float* __restrict__ nodes, float* __restrict__ nodes_out) {
    __shared__ float sW[L * KEFF];   // [j][k], 12 KB
    __shared__ float sB[L];
    __shared__ float sD[L];

    int tid = threadIdx.x;
    for (int i = tid; i < L * KEFF; i += blockDim.x) sW[i] = g_W1eff[i];
    if (tid < L) {
        sB[tid] = g_b1eff[tid];
        sD[tid] = g_w2d[tid];
    }
    __syncthreads();

    int n = blockIdx.x * blockDim.x + tid;
    if (n >= NN) return;

    // gather 24 inputs into registers
    float in[KEFF];
    {
        const float4* np = reinterpret_cast<const float4*>(nodes + (size_t)n * 16);
#pragma unroll
        for (int q = 0; q < 4; q++) {
            float4 v = __ldg(np + q);
            in[4 * q + 0] = v.x;
            in[4 * q + 1] = v.y;
            in[4 * q + 2] = v.z;
            in[4 * q + 3] = v.w;
        }
        float4 a = *reinterpret_cast<const float4*>(g_aggs + 4 * n);
        float4 b = *reinterpret_cast<const float4*>(g_aggr + 4 * n);
        in[16] = a.x; in[17] = a.y; in[18] = a.z; in[19] = a.w;
        in[20] = b.x; in[21] = b.y; in[22] = b.z; in[23] = b.w;
    }

    float out = g_cd[0];
#pragma unroll 4
    for (int j = 0; j < L; j++) {
        const float4* wr = reinterpret_cast<const float4*>(sW + j * KEFF);
        float acc = sB[j];
#pragma unroll
        for (int q = 0; q < 6; q++) {
            float4 w = wr[q];
            acc = fmaf(in[4 * q + 0], w.x, acc);
            acc = fmaf(in[4 * q + 1], w.y, acc);
            acc = fmaf(in[4 * q + 2], w.z, acc);
            acc = fmaf(in[4 * q + 3], w.w, acc);
        }
        out = fmaf(fmaxf(acc, 0.f), sD[j], out);
    }
    nodes_out[n] = out;
}

// ---------------------------------------------------------------------------
extern "C" void kernel_launch(void* const* d_in, const int* in_sizes, int n_in,
                              void* d_out, int out_size) {
    const float* nodes     = (const float*)d_in[0];
    const float* edges     = (const float*)d_in[1];
    const float* globals_  = (const float*)d_in[2];
    const int*   senders   = (const int*)d_in[3];
    const int*   receivers = (const int*)d_in[4];
    const float* W_en = (const float*)d_in[5];
    const float* b_en = (const float*)d_in[6];
    const float* W_ee = (const float*)d_in[7];
    const float* b_ee = (const float*)d_in[8];
    const float* W1   = (const float*)d_in[9];
    const float* b1   = (const float*)d_in[10];
    const float* W2   = (const float*)d_in[11];
    const float* b2   = (const float*)d_in[12];
    const float* W_dn = (const float*)d_in[13];
    const float* b_dn = (const float*)d_in[14];
    const float* W_de = (const float*)d_in[15];
    const float* b_de = (const float*)d_in[16];

    float* out = (float*)d_out;
    float* nodes_out = out;          // [50000]
    float* edges_out = out + NN;     // [800000]

    prep_kernel<<<64, 256>>>(globals_, W_en, b_en, W_ee, b_ee, W1, b1, W2, b2,
                             W_dn, b_dn, W_de, b_de);
    edge_kernel<<<(NE + 255) / 256, 256>>>(edges, senders, receivers,
                                           edges_out);
    node_kernel<<<(NN + 255) / 256, 256>>>(nodes, nodes_out);
}

// round 3
// speedup vs baseline: 8.7229x; 1.2076x over previous
#include <cuda_runtime.h>

#define NN 50000
#define NE 800000
#define L 128
#define KEFF 24   // 16 node feats + 3 agg_s + 1 cnt_s + 3 agg_r + 1 cnt_r

// Scratch (__device__ globals; no allocation allowed)
__device__ float g_agg[NN * 8];       // per node: {s0,s1,s2,cnt_s, r0,r1,r2,cnt_r}
__device__ float g_W1eff[L * KEFF];   // [j*24+k] folded layer-1 weight
__device__ float g_b1eff[L];          // folded layer-1 bias
__device__ float g_w2d[L];            // W2 @ W_dn
__device__ float g_cd[1];             // b2.W_dn + b_dn

// f32x2 packed helpers ------------------------------------------------------
__device__ __forceinline__ unsigned long long pk2(float lo, float hi) {
    unsigned long long r;
    asm("mov.b64 %0, {%1, %2};" : "=l"(r) : "f"(lo), "f"(hi));
    return r;
}
__device__ __forceinline__ void upk2(unsigned long long v, float& lo, float& hi) {
    asm("mov.b64 {%0, %1}, %2;" : "=f"(lo), "=f"(hi) : "l"(v));
}
#define FMA2(d, a, b, c) \
    asm("fma.rn.f32x2 %0, %1, %2, %3;" : "=l"(d) : "l"(a), "l"(b), "l"(c))

__device__ __forceinline__ float warp_sum(float v) {
#pragma unroll
    for (int o = 16; o; o >>= 1) v += __shfl_xor_sync(0xffffffffu, v, o);
    return v;
}

// ---------------------------------------------------------------------------
// Edge pass + embedded prep folds.
//   - every block: inline 4-dot edge-decoder fold in smem, then 1 edge/thread
//   - blocks 0..416: one warp per folded-weight output (3329 outputs total)
__global__ __launch_bounds__(256) void edge_kernel(
    const float* __restrict__ edges, const int* __restrict__ senders,
    const int* __restrict__ receivers, float* __restrict__ edges_out,
    const float* __restrict__ g, const float* __restrict__ W_en,
    const float* __restrict__ b_en, const float* __restrict__ W_ee,
    const float* __restrict__ b_ee, const float* __restrict__ W1,
    const float* __restrict__ b1, const float* __restrict__ W2,
    const float* __restrict__ b2, const float* __restrict__ W_dn,
    const float* __restrict__ b_dn, const float* __restrict__ W_de,
    const float* __restrict__ b_de) {
    __shared__ float s_edec[4];
    int tid = threadIdx.x;
    int lane = tid & 31;
    int warp = tid >> 5;

    // --- per-block edge-decoder fold: edec[i] = W_ee[i,:].W_de ; edec[3]=bias
    if (warp < 4) {
        float acc = 0.f;
        if (warp < 3) {
#pragma unroll
            for (int q = 0; q < 4; q++) {
                int m = lane + 32 * q;
                acc += W_ee[warp * L + m] * W_de[m];
            }
        } else {
#pragma unroll
            for (int q = 0; q < 4; q++) {
                int m = lane + 32 * q;
                acc += b_ee[m] * W_de[m];
            }
        }
        acc = warp_sum(acc);
        if (lane == 0) s_edec[warp] = (warp == 3) ? acc + b_de[0] : acc;
    }

    // --- distributed prep: one warp per folded output -----------------------
    int gw = blockIdx.x * 8 + warp;
    if (gw < L * KEFF) {                      // W1eff[id=k*128+j]
        int k = gw >> 7;
        int j = gw & (L - 1);
        const float* A;
        int base;
        if (k < 16)      { A = W_en + k * L;        base = 0; }
        else if (k < 19) { A = W_ee + (k - 16) * L; base = L; }
        else if (k == 19){ A = b_ee;                base = L; }
        else if (k < 23) { A = W_ee + (k - 20) * L; base = 2 * L; }
        else             { A = b_ee;                base = 2 * L; }
        float acc = 0.f;
#pragma unroll
        for (int q = 0; q < 4; q++) {
            int m = lane + 32 * q;
            acc += A[m] * W1[(size_t)(base + m) * L + j];
        }
        acc = warp_sum(acc);
        if (lane == 0) g_W1eff[j * KEFF + k] = acc;
    } else if (gw < L * KEFF + L) {           // b1eff[j]
        int j = gw - L * KEFF;
        float acc = 0.f;
#pragma unroll
        for (int q = 0; q < 4; q++) {
            int m = lane + 32 * q;
            acc += b_en[m] * W1[(size_t)m * L + j];
        }
        if (lane < 8) acc += g[lane] * W1[(size_t)(3 * L + lane) * L + j];
        acc = warp_sum(acc);
        if (lane == 0) g_b1eff[j] = acc + b1[j];
    } else if (gw < L * KEFF + 2 * L) {       // w2d[k]
        int k = gw - L * KEFF - L;
        float acc = 0.f;
#pragma unroll
        for (int q = 0; q < 4; q++) {
            int j = lane + 32 * q;
            acc += W2[(size_t)k * L + j] * W_dn[j];
        }
        acc = warp_sum(acc);
        if (lane == 0) g_w2d[k] = acc;
    } else if (gw == L * KEFF + 2 * L) {      // cd
        float acc = 0.f;
#pragma unroll
        for (int q = 0; q < 4; q++) {
            int j = lane + 32 * q;
            acc += b2[j] * W_dn[j];
        }
        acc = warp_sum(acc);
        if (lane == 0) g_cd[0] = acc + b_dn[0];
    }
    __syncthreads();

    // --- edge work ----------------------------------------------------------
    int e = blockIdx.x * blockDim.x + tid;
    if (e >= NE) return;

    float w0 = s_edec[0], w1 = s_edec[1], w2 = s_edec[2], c = s_edec[3];

    float x0 = __ldg(edges + 3 * e + 0);
    float x1 = __ldg(edges + 3 * e + 1);
    float x2 = __ldg(edges + 3 * e + 2);
    int s = senders[e];
    int r = receivers[e];

    float* ps = g_agg + (size_t)8 * s;
    float* pr = g_agg + (size_t)8 * r + 4;
    asm volatile("red.global.add.v4.f32 [%0], {%1, %2, %3, %4};" ::"l"(ps),
                 "f"(x0), "f"(x1), "f"(x2), "f"(1.0f)
                 : "memory");
    asm volatile("red.global.add.v4.f32 [%0], {%1, %2, %3, %4};" ::"l"(pr),
                 "f"(x0), "f"(x1), "f"(x2), "f"(1.0f)
                 : "memory");

    edges_out[e] = fmaf(x0, w0, fmaf(x1, w1, fmaf(x2, w2, c)));
}

// ---------------------------------------------------------------------------
// Node pass: node-PAIR per thread using packed fma.rn.f32x2.
__global__ __launch_bounds__(256) void node_kernel(
    const float* __restrict__ nodes, float* __restrict__ nodes_out) {
    __shared__ unsigned long long sWp[L * KEFF];  // {w,w} packed, 24 KB
    __shared__ unsigned long long sBp[L];
    __shared__ unsigned long long sDp[L];

    int tid = threadIdx.x;
    for (int i = tid; i < L * KEFF; i += blockDim.x) {
        float w = g_W1eff[i];
        sWp[i] = pk2(w, w);
    }
    if (tid < L) {
        float b = g_b1eff[tid];
        sBp[tid] = pk2(b, b);
        float d = g_w2d[tid];
        sDp[tid] = pk2(d, d);
    }
    __syncthreads();

    int t = blockIdx.x * blockDim.x + tid;  // pair index
    int n0 = 2 * t;
    if (n0 >= NN) return;                   // NN even -> n0+1 always valid

    unsigned long long in2[KEFF];
    {
        const float4* a = reinterpret_cast<const float4*>(nodes + (size_t)n0 * 16);
        const float4* b = reinterpret_cast<const float4*>(nodes + (size_t)(n0 + 1) * 16);
#pragma unroll
        for (int q = 0; q < 4; q++) {
            float4 va = __ldg(a + q);
            float4 vb = __ldg(b + q);
            in2[4 * q + 0] = pk2(va.x, vb.x);
            in2[4 * q + 1] = pk2(va.y, vb.y);
            in2[4 * q + 2] = pk2(va.z, vb.z);
            in2[4 * q + 3] = pk2(va.w, vb.w);
        }
        const float4* pa = reinterpret_cast<const float4*>(g_agg + (size_t)8 * n0);
        const float4* pb = reinterpret_cast<const float4*>(g_agg + (size_t)8 * (n0 + 1));
        float4 a0 = pa[0], a1 = pa[1];
        float4 b0 = pb[0], b1 = pb[1];
        in2[16] = pk2(a0.x, b0.x); in2[17] = pk2(a0.y, b0.y);
        in2[18] = pk2(a0.z, b0.z); in2[19] = pk2(a0.w, b0.w);
        in2[20] = pk2(a1.x, b1.x); in2[21] = pk2(a1.y, b1.y);
        in2[22] = pk2(a1.z, b1.z); in2[23] = pk2(a1.w, b1.w);
    }

    float cd = g_cd[0];
    unsigned long long out2 = pk2(cd, cd);

#pragma unroll 2
    for (int j = 0; j < L; j++) {
        unsigned long long acc = sBp[j];
        const ulonglong2* wr = reinterpret_cast<const ulonglong2*>(sWp + j * KEFF);
#pragma unroll
        for (int q = 0; q < 12; q++) {
            ulonglong2 w = wr[q];
            FMA2(acc, in2[2 * q + 0], w.x, acc);
            FMA2(acc, in2[2 * q + 1], w.y, acc);
        }
        float lo, hi;
        upk2(acc, lo, hi);
        unsigned long long r2 = pk2(fmaxf(lo, 0.f), fmaxf(hi, 0.f));
        FMA2(out2, r2, sDp[j], out2);
    }

    float o0, o1;
    upk2(out2, o0, o1);
    nodes_out[n0] = o0;
    nodes_out[n0 + 1] = o1;
}

// ---------------------------------------------------------------------------
extern "C" void kernel_launch(void* const* d_in, const int* in_sizes, int n_in,
                              void* d_out, int out_size) {
    const float* nodes     = (const float*)d_in[0];
    const float* edges     = (const float*)d_in[1];
    const float* globals_  = (const float*)d_in[2];
    const int*   senders   = (const int*)d_in[3];
    const int*   receivers = (const int*)d_in[4];
    const float* W_en = (const float*)d_in[5];
    const float* b_en = (const float*)d_in[6];
    const float* W_ee = (const float*)d_in[7];
    const float* b_ee = (const float*)d_in[8];
    const float* W1   = (const float*)d_in[9];
    const float* b1   = (const float*)d_in[10];
    const float* W2   = (const float*)d_in[11];
    const float* b2   = (const float*)d_in[12];
    const float* W_dn = (const float*)d_in[13];
    const float* b_dn = (const float*)d_in[14];
    const float* W_de = (const float*)d_in[15];
    const float* b_de = (const float*)d_in[16];

    float* out = (float*)d_out;
    float* nodes_out = out;          // [50000]
    float* edges_out = out + NN;     // [800000]

    void* agg_ptr = nullptr;
    cudaGetSymbolAddress(&agg_ptr, g_agg);
    cudaMemsetAsync(agg_ptr, 0, (size_t)NN * 8 * sizeof(float), 0);

    edge_kernel<<<(NE + 255) / 256, 256>>>(
        edges, senders, receivers, edges_out, globals_, W_en, b_en, W_ee, b_ee,
        W1, b1, W2, b2, W_dn, b_dn, W_de, b_de);
    node_kernel<<<(NN / 2 + 255) / 256, 256>>>(nodes, nodes_out);
}